// round 7
// baseline (speedup 1.0000x reference)
#include <cuda_runtime.h>
#include <cuda_bf16.h>
#include <math.h>
#include <stdint.h>

#define NH 4
#define HD 128
#define D  512
#define TS 24
#define NB 64
#define NPOS 32768
#define J   96
#define JP  104
#define TILE_BYTES 53248      /* 128 rows x 208B, hi then lo (26624 each) */
#define LO_OFF     26624

// ---------------- device scratch ----------------
__device__ __align__(16)  float g_A [NB*NH*HD];
__device__ __align__(16)  float g_Bq[TS*NH*HD];
__device__ __align__(16)  float g_K [TS*NH*HD];
__device__ __align__(16)  float g_V [TS*NH*HD];
__device__ __align__(16)  float g_E [NB*TS*NH*TS];
__device__ __align__(128) __nv_bfloat16 g_Bh[D*JP];   // VU^T hi: [d][j]
__device__ __align__(128) __nv_bfloat16 g_Bl[D*JP];   // VU^T lo
__device__ __align__(16)  float g_TL[J*TS];
__device__ __align__(128) char g_At[256*TILE_BYTES];  // bf16 A tiles, smem image

// ---------------- helpers ----------------
__device__ __forceinline__ uint32_t smem_u32(const void* p){
    uint32_t a;
    asm("{ .reg .u64 t; cvta.to.shared.u64 t, %1; cvt.u32.u64 %0, t; }" : "=r"(a) : "l"(p));
    return a;
}
__device__ __forceinline__ void bulk_g2s(uint32_t dst, const void* src,
                                         uint32_t bytes, uint32_t mbar){
    asm volatile(
        "cp.async.bulk.shared::cluster.global.mbarrier::complete_tx::bytes [%0], [%1], %2, [%3];"
        :: "r"(dst), "l"(src), "r"(bytes), "r"(mbar) : "memory");
}
#define MBAR_INIT(a, c)  asm volatile("mbarrier.init.shared.b64 [%0], %1;" :: "r"(a), "r"(c) : "memory")
#define MBAR_EXPECT(a,b) asm volatile("mbarrier.arrive.expect_tx.shared.b64 _, [%0], %1;" :: "r"(a), "r"(b) : "memory")
#define MBAR_WAIT(a, ph) do { \
    uint32_t _m=(a), _p=(ph), _d; \
    asm volatile("{\n\t.reg .pred p;\n\t" \
        "mbarrier.try_wait.parity.acquire.cta.shared::cta.b64 p, [%1], %2;\n\t" \
        "selp.b32 %0, 1, 0, p;\n\t}" : "=r"(_d) : "r"(_m), "r"(_p) : "memory"); \
    if (!_d) { asm volatile("{\n\t.reg .pred P1;\n\t" \
        "W_%=:\n\tmbarrier.try_wait.parity.acquire.cta.shared::cta.b64 P1, [%0], %1, 0x989680;\n\t" \
        "@P1 bra.uni WD_%=;\n\tbra.uni W_%=;\n\tWD_%=:\n\t}" :: "r"(_m), "r"(_p) : "memory"); } \
} while(0)

#define MMA16816(c, a, b0v, b1v) \
    asm volatile("mma.sync.aligned.m16n8k16.row.col.f32.bf16.bf16.f32 " \
        "{%0,%1,%2,%3}, {%4,%5,%6,%7}, {%8,%9}, {%0,%1,%2,%3};" \
        : "+f"((c)[0]), "+f"((c)[1]), "+f"((c)[2]), "+f"((c)[3]) \
        : "r"((a)[0]), "r"((a)[1]), "r"((a)[2]), "r"((a)[3]), \
          "r"(b0v), "r"(b1v))

#define LDMX4(r, addr) \
    asm volatile("ldmatrix.sync.aligned.m8n8.x4.shared.b16 {%0,%1,%2,%3}, [%4];" \
        : "=r"((r)[0]), "=r"((r)[1]), "=r"((r)[2]), "=r"((r)[3]) : "r"(addr))

__device__ __forceinline__ float wredsum(float v){
    #pragma unroll
    for (int o = 16; o; o >>= 1) v += __shfl_xor_sync(0xFFFFFFFFu, v, o);
    return v;
}
__device__ __forceinline__ float dot4(float4 a, float4 b){
    return fmaf(a.x,b.x, fmaf(a.y,b.y, fmaf(a.z,b.z, a.w*b.w)));
}

// ---------------- K1: A, Bq, K, V ----------------
__global__ void __launch_bounds__(256)
k_pre1(const float* __restrict__ ts_emb, const int* __restrict__ user_x,
       const float* __restrict__ upt,
       const float* __restrict__ Wq, const float* __restrict__ bq,
       const float* __restrict__ Wk, const float* __restrict__ bk,
       const float* __restrict__ Wv, const float* __restrict__ bv)
{
    const int wid  = threadIdx.x >> 5;
    const int lane = threadIdx.x & 31;
    const int rg   = blockIdx.x >> 6;
    const int he   = (blockIdx.x & 63)*8 + wid;

    const float* w;
    const float* x[8];
    float bias = 0.f;
    float* dst;
    int row0;
    if (rg < 8) {
        w = Wq + (size_t)he*1024; dst = g_A; row0 = rg*8;
        #pragma unroll
        for (int i = 0; i < 8; i++)
            x[i] = upt + (size_t)__ldg(user_x + rg*8 + i)*D;
    } else if (rg < 11) {
        int g = rg - 8;
        w = Wq + (size_t)he*1024 + 512; bias = __ldg(bq + he);
        dst = g_Bq; row0 = g*8;
        #pragma unroll
        for (int i = 0; i < 8; i++) x[i] = ts_emb + (g*8 + i)*D;
    } else if (rg < 14) {
        int g = rg - 11;
        w = Wk + (size_t)he*512; bias = __ldg(bk + he);
        dst = g_K; row0 = g*8;
        #pragma unroll
        for (int i = 0; i < 8; i++) x[i] = ts_emb + (g*8 + i)*D;
    } else {
        int g = rg - 14;
        w = Wv + (size_t)he*512; bias = __ldg(bv + he);
        dst = g_V; row0 = g*8;
        #pragma unroll
        for (int i = 0; i < 8; i++) x[i] = ts_emb + (g*8 + i)*D;
    }

    float acc[8] = {0,0,0,0,0,0,0,0};
    #pragma unroll
    for (int ch = 0; ch < 4; ch++) {
        int e = ch*128 + lane*4;
        float4 w4 = __ldg((const float4*)(w + e));
        #pragma unroll
        for (int i = 0; i < 8; i++) {
            float4 x4 = __ldg((const float4*)(x[i] + e));
            acc[i] = fmaf(w4.x,x4.x, fmaf(w4.y,x4.y, fmaf(w4.z,x4.z, fmaf(w4.w,x4.w, acc[i]))));
        }
    }
    float r = 0.f;
    #pragma unroll
    for (int i = 0; i < 8; i++) {
        float s = wredsum(acc[i]);
        if (lane == i) r = s;
    }
    if (lane < 8)
        dst[(size_t)(row0 + lane)*D + he] = r + bias;
}

// ---------------- K23: (pre2) VU/TL folds  +  (pre3) E table, one launch ----------------
__global__ void __launch_bounds__(256)
k_pre23(const float* __restrict__ Wu, const float* __restrict__ Wt)
{
    const int wid  = threadIdx.x >> 5;
    const int lane = threadIdx.x & 31;
    if (blockIdx.x < 804) {
        int task = blockIdx.x*8 + wid;
        if (task < 6144) {
            int j  = task >> 6;
            int dg = task & 63;
            int h = j / TS, k = j - h*TS;
            float4 vr = *(const float4*)(g_V + (k*NH + h)*HD + lane*4);
            const float* wbase = Wu + h*HD + lane*4;
            float val = 0.f;
            #pragma unroll
            for (int dd = 0; dd < 8; dd++) {
                int d = dg*8 + dd;
                float4 w4 = __ldg((const float4*)(wbase + (size_t)d*D));
                float s = wredsum(dot4(vr, w4));
                if (lane == dd) val = s;
            }
            if (lane < 8) {
                int d = dg*8 + lane;
                __nv_bfloat16 hi = __float2bfloat16(val);
                __nv_bfloat16 lo = __float2bfloat16(val - __bfloat162float(hi));
                g_Bh[(size_t)d*JP + j] = hi;
                g_Bl[(size_t)d*JP + j] = lo;
            }
        } else if (task < 6144 + 288) {
            int t2 = task - 6144;
            int j  = t2 / 3;
            int dg = t2 - j*3;
            int h = j / TS, k = j - h*TS;
            float4 vr = *(const float4*)(g_V + (k*NH + h)*HD + lane*4);
            const float* wbase = Wt + h*HD + lane*4;
            float val = 0.f;
            #pragma unroll
            for (int dd = 0; dd < 8; dd++) {
                int d = dg*8 + dd;
                float4 w4 = __ldg((const float4*)(wbase + (size_t)d*D));
                float s = wredsum(dot4(vr, w4));
                if (lane == dd) val = s;
            }
            if (lane < 8)
                g_TL[j*TS + dg*8 + lane] = val;
        }
    } else {
        int blk = blockIdx.x - 804;       // 768 blocks: E table
        int b   = blk / 12;
        int rem = blk - b*12;
        int h   = rem / 3;
        int tg  = rem - h*3;
        int t   = tg*8 + wid;

        float4 qa = *(const float4*)(g_A  + (b*NH + h)*HD + lane*4);
        float4 qb = *(const float4*)(g_Bq + (t*NH + h)*HD + lane*4);
        float4 q = make_float4(qa.x+qb.x, qa.y+qb.y, qa.z+qb.z, qa.w+qb.w);

        float val = 0.f;
        #pragma unroll
        for (int k = 0; k < TS; k++) {
            float4 kv = *(const float4*)(g_K + (k*NH + h)*HD + lane*4);
            float s = wredsum(dot4(q, kv));
            if (lane == k) val = s;
        }
        if (lane < TS)
            g_E[((size_t)(b*TS + t)*NH + h)*TS + lane] = expf(val * 0.08838834764831845f);
    }
}

// ---------------- K_attn: softmax -> A tiles (bf16 hi/lo) + time logits ----------------
__global__ void __launch_bounds__(512)
k_attn(const int* __restrict__ hour_x, const int* __restrict__ hour_mask,
       const float* __restrict__ b_time, float* __restrict__ out_tl)
{
    __shared__ float stl[J*TS];
    const int tid = threadIdx.x;
    const int p = tid >> 2;          // position in tile
    const int h = tid & 3;           // head
    const int tile = blockIdx.x;
    const int n = tile*128 + p;

    for (int i = tid; i < J*TS; i += 512) stl[i] = g_TL[i];
    __syncthreads();

    // masked softmax, all in registers
    const int b = n >> 9;
    const int t = __ldg(hour_x + n);
    const float4* erow = (const float4*)(g_E + ((size_t)(b*TS + t)*NH + h)*TS);
    const int4*   mrow = (const int4*)(hour_mask + (size_t)n*TS);
    float wv[TS]; float sum = 0.f;
    #pragma unroll
    for (int q = 0; q < 6; q++) {
        int4   m = __ldg(mrow + q);
        float4 e = erow[q];
        wv[4*q+0] = (m.x == 1) ? 0.f : e.x;
        wv[4*q+1] = (m.y == 1) ? 0.f : e.y;
        wv[4*q+2] = (m.z == 1) ? 0.f : e.z;
        wv[4*q+3] = (m.w == 1) ? 0.f : e.w;
        sum += (wv[4*q+0]+wv[4*q+1]) + (wv[4*q+2]+wv[4*q+3]);
    }
    const float inv = 1.f / sum;
    #pragma unroll
    for (int k = 0; k < TS; k++) wv[k] *= inv;

    // write A tile fragment: 24 bf16 hi + 24 lo at row p, cols h*24..h*24+23
    {
        uint32_t hiw[12], low[12];
        #pragma unroll
        for (int q = 0; q < 12; q++) {
            float a0 = wv[2*q], a1 = wv[2*q+1];
            __nv_bfloat16 h0 = __float2bfloat16(a0);
            __nv_bfloat16 h1 = __float2bfloat16(a1);
            __nv_bfloat16 l0 = __float2bfloat16(a0 - __bfloat162float(h0));
            __nv_bfloat16 l1 = __float2bfloat16(a1 - __bfloat162float(h1));
            hiw[q] = (uint32_t)__bfloat16_as_ushort(h1) << 16 | __bfloat16_as_ushort(h0);
            low[q] = (uint32_t)__bfloat16_as_ushort(l1) << 16 | __bfloat16_as_ushort(l0);
        }
        char* base = g_At + (size_t)tile*TILE_BYTES + p*208 + h*48;
        uint4* dh = (uint4*)base;
        uint4* dl = (uint4*)(base + LO_OFF);
        dh[0] = make_uint4(hiw[0],hiw[1],hiw[2],hiw[3]);
        dh[1] = make_uint4(hiw[4],hiw[5],hiw[6],hiw[7]);
        dh[2] = make_uint4(hiw[8],hiw[9],hiw[10],hiw[11]);
        dl[0] = make_uint4(low[0],low[1],low[2],low[3]);
        dl[1] = make_uint4(low[4],low[5],low[6],low[7]);
        dl[2] = make_uint4(low[8],low[9],low[10],low[11]);
    }

    // time logits: per-head partial, butterfly across 4 h-lanes
    float tlp[TS];
    #pragma unroll
    for (int d = 0; d < TS; d++) tlp[d] = 0.f;
    #pragma unroll 4
    for (int k = 0; k < TS; k++) {
        float a = wv[k];
        const float* tr = stl + (h*TS + k)*TS;
        #pragma unroll
        for (int d = 0; d < TS; d++) tlp[d] = fmaf(a, tr[d], tlp[d]);
    }
    #pragma unroll
    for (int d = 0; d < TS; d++) {
        tlp[d] += __shfl_xor_sync(0xFFFFFFFFu, tlp[d], 1);
        tlp[d] += __shfl_xor_sync(0xFFFFFFFFu, tlp[d], 2);
    }
    {
        float* orow = out_tl + (size_t)n*TS + h*6;
        #pragma unroll
        for (int i = 0; i < 6; i++)
            orow[i] = tlp[h*6 + i] + __ldg(b_time + h*6 + i);
    }
}

// ---------------- K_gemm: pure HMMA GEMM, B resident, A streamed ----------------
#define GM_MBAR  0          /* B mbar @0, A mbars @8, @16 */
#define GM_B     128        /* 53248 (hi + lo) */
#define GM_A     53376      /* 2 x 53248 */
#define GM_TOTAL 159872

__global__ void __launch_bounds__(512, 1)
k_gemm(const float* __restrict__ b_unify, float* __restrict__ out_emb)
{
    extern __shared__ char sm[];
    const uint32_t sb = smem_u32(sm);
    const int tid  = threadIdx.x;
    const int wid  = tid >> 5;
    const int lane = tid & 31;
    const int c    = blockIdx.x & 3;     // N-chunk
    const int mg   = blockIdx.x >> 2;    // M-group: tiles mg*4 .. mg*4+3

    if (tid == 0) {
        MBAR_INIT(sb + GM_MBAR,      1);
        MBAR_INIT(sb + GM_MBAR + 8,  1);
        MBAR_INIT(sb + GM_MBAR + 16, 1);
        // B chunk (hi+lo), resident
        MBAR_EXPECT(sb + GM_MBAR, TILE_BYTES);
        bulk_g2s(sb + GM_B,          g_Bh + (size_t)c*128*JP, 26624, sb + GM_MBAR);
        bulk_g2s(sb + GM_B + LO_OFF, g_Bl + (size_t)c*128*JP, 26624, sb + GM_MBAR);
        // A tiles 0,1
        #pragma unroll
        for (int i = 0; i < 2; i++) {
            MBAR_EXPECT(sb + GM_MBAR + 8 + 8*i, TILE_BYTES);
            bulk_g2s(sb + GM_A + i*TILE_BYTES,
                     g_At + (size_t)(mg*4 + i)*TILE_BYTES, TILE_BYTES,
                     sb + GM_MBAR + 8 + 8*i);
        }
    }
    __syncthreads();

    const int wm = wid & 3, wn = wid >> 2;
    const int grp = lane >> 2, qid = lane & 3;
    const int am = lane >> 3, r8 = lane & 7;

    const uint32_t aRow = (uint32_t)(wm*32 + (am & 1)*8 + r8)*208u + (uint32_t)((am >> 1) & 1)*16u;
    const uint32_t bRow = (uint32_t)(wn*32 + ((am >> 1) & 1)*8 + r8)*208u + (uint32_t)(am & 1)*16u;
    const uint32_t bBase = sb + GM_B + bRow;

    // bias for this warp's columns (pre-load once)
    float bx[4], by[4];
    #pragma unroll
    for (int nt = 0; nt < 4; nt++) {
        int d = c*128 + wn*32 + nt*8 + qid*2;
        bx[nt] = __ldg(b_unify + d);
        by[nt] = __ldg(b_unify + d + 1);
    }

    MBAR_WAIT(sb + GM_MBAR, 0);   // B ready

    for (int i = 0; i < 4; i++) {
        const int s = i & 1;
        MBAR_WAIT(sb + GM_MBAR + 8 + 8*s, (i >> 1) & 1);
        const uint32_t aBase = sb + GM_A + (uint32_t)s*TILE_BYTES + aRow;

        float acc[2][4][4];
        #pragma unroll
        for (int mt = 0; mt < 2; mt++)
            #pragma unroll
            for (int nt = 0; nt < 4; nt++)
                #pragma unroll
                for (int k = 0; k < 4; k++) acc[mt][nt][k] = 0.f;

        #pragma unroll
        for (int ks = 0; ks < 6; ks++) {
            const uint32_t ak = aBase + ks*32;
            const uint32_t bk = bBase + ks*32;
            uint32_t ah[2][4], al[2][4], bh[2][4], bl[2][4];
            LDMX4(ah[0], ak);
            LDMX4(ah[1], ak + 16*208);
            LDMX4(al[0], ak + LO_OFF);
            LDMX4(al[1], ak + LO_OFF + 16*208);
            LDMX4(bh[0], bk);
            LDMX4(bh[1], bk + 16*208);
            LDMX4(bl[0], bk + LO_OFF);
            LDMX4(bl[1], bk + LO_OFF + 16*208);
            #pragma unroll
            for (int mt = 0; mt < 2; mt++)
                #pragma unroll
                for (int nt = 0; nt < 4; nt++) {
                    const int pr = nt >> 1, sub = (nt & 1)*2;
                    MMA16816(acc[mt][nt], ah[mt], bh[pr][sub], bh[pr][sub+1]);
                    MMA16816(acc[mt][nt], ah[mt], bl[pr][sub], bl[pr][sub+1]);
                    MMA16816(acc[mt][nt], al[mt], bh[pr][sub], bh[pr][sub+1]);
                }
        }

        const int rowBase = (mg*4 + i)*128 + wm*32;
        #pragma unroll
        for (int nt = 0; nt < 4; nt++) {
            int d = c*128 + wn*32 + nt*8 + qid*2;
            #pragma unroll
            for (int mt = 0; mt < 2; mt++) {
                int row = rowBase + mt*16 + grp;
                float2 o0 = make_float2(acc[mt][nt][0] + bx[nt], acc[mt][nt][1] + by[nt]);
                float2 o1 = make_float2(acc[mt][nt][2] + bx[nt], acc[mt][nt][3] + by[nt]);
                *(float2*)(out_emb + (size_t)row*D + d)     = o0;
                *(float2*)(out_emb + (size_t)(row+8)*D + d) = o1;
            }
        }
        __syncthreads();
        if (tid == 0 && i + 2 < 4) {
            MBAR_EXPECT(sb + GM_MBAR + 8 + 8*s, TILE_BYTES);
            bulk_g2s(sb + GM_A + s*TILE_BYTES,
                     g_At + (size_t)(mg*4 + i + 2)*TILE_BYTES, TILE_BYTES,
                     sb + GM_MBAR + 8 + 8*s);
        }
    }
}

// ---------------- launch ----------------
extern "C" void kernel_launch(void* const* d_in, const int* in_sizes, int n_in,
                              void* d_out, int out_size)
{
    const float* ts_emb    = (const float*)d_in[0];
    const int*   user_x    = (const int*)  d_in[3];
    const int*   hour_x    = (const int*)  d_in[4];
    const int*   hour_mask = (const int*)  d_in[5];
    const float* upt       = (const float*)d_in[6];
    const float* Wq        = (const float*)d_in[7];
    const float* bq        = (const float*)d_in[8];
    const float* Wk        = (const float*)d_in[9];
    const float* bk        = (const float*)d_in[10];
    const float* Wv        = (const float*)d_in[11];
    const float* bv        = (const float*)d_in[12];
    const float* Wu        = (const float*)d_in[13];
    const float* bu        = (const float*)d_in[14];
    const float* Wt        = (const float*)d_in[15];
    const float* bt        = (const float*)d_in[16];

    float* out_emb = (float*)d_out;
    float* out_tl  = out_emb + (size_t)NPOS * D;

    cudaFuncSetAttribute(k_gemm, cudaFuncAttributeMaxDynamicSharedMemorySize, GM_TOTAL);

    k_pre1<<<1088, 256>>>(ts_emb, user_x, upt, Wq, bq, Wk, bk, Wv, bv);
    k_pre23<<<1572, 256>>>(Wu, Wt);
    k_attn<<<256, 512>>>(hour_x, hour_mask, bt, out_tl);
    k_gemm<<<256, 512, GM_TOTAL>>>(bu, out_emb);
}

// round 8
// speedup vs baseline: 1.2554x; 1.2554x over previous
#include <cuda_runtime.h>
#include <cuda_bf16.h>
#include <math.h>
#include <stdint.h>

#define NH 4
#define HD 128
#define D  512
#define TS 24
#define NB 64
#define NPOS 32768
#define J   96
#define JP  104

// ---------------- device scratch ----------------
__device__ __align__(16)  float g_A [NB*NH*HD];
__device__ __align__(16)  float g_Bq[TS*NH*HD];
__device__ __align__(16)  float g_K [TS*NH*HD];
__device__ __align__(16)  float g_V [TS*NH*HD];
__device__ __align__(16)  float g_E [NB*TS*NH*TS];
__device__ __align__(128) __nv_bfloat16 g_Bh[D*JP];   // VU^T hi: [d][j] (208B rows)
__device__ __align__(128) __nv_bfloat16 g_Bl[D*JP];   // VU^T lo
__device__ __align__(16)  float g_TL[J*TS];

// ---------------- helpers ----------------
__device__ __forceinline__ uint32_t smem_u32(const void* p){
    uint32_t a;
    asm("{ .reg .u64 t; cvta.to.shared.u64 t, %1; cvt.u32.u64 %0, t; }" : "=r"(a) : "l"(p));
    return a;
}
__device__ __forceinline__ void bulk_g2s(uint32_t dst, const void* src,
                                         uint32_t bytes, uint32_t mbar){
    asm volatile(
        "cp.async.bulk.shared::cluster.global.mbarrier::complete_tx::bytes [%0], [%1], %2, [%3];"
        :: "r"(dst), "l"(src), "r"(bytes), "r"(mbar) : "memory");
}
#define MBAR_INIT(a, c)  asm volatile("mbarrier.init.shared.b64 [%0], %1;" :: "r"(a), "r"(c) : "memory")
#define MBAR_EXPECT(a,b) asm volatile("mbarrier.arrive.expect_tx.shared.b64 _, [%0], %1;" :: "r"(a), "r"(b) : "memory")
#define MBAR_WAIT(a, ph) do { \
    uint32_t _m=(a), _p=(ph), _d; \
    asm volatile("{\n\t.reg .pred p;\n\t" \
        "mbarrier.try_wait.parity.acquire.cta.shared::cta.b64 p, [%1], %2;\n\t" \
        "selp.b32 %0, 1, 0, p;\n\t}" : "=r"(_d) : "r"(_m), "r"(_p) : "memory"); \
    if (!_d) { asm volatile("{\n\t.reg .pred P1;\n\t" \
        "W_%=:\n\tmbarrier.try_wait.parity.acquire.cta.shared::cta.b64 P1, [%0], %1, 0x989680;\n\t" \
        "@P1 bra.uni WD_%=;\n\tbra.uni W_%=;\n\tWD_%=:\n\t}" :: "r"(_m), "r"(_p) : "memory"); } \
} while(0)

#define MMA16816(c, a, b0v, b1v) \
    asm volatile("mma.sync.aligned.m16n8k16.row.col.f32.bf16.bf16.f32 " \
        "{%0,%1,%2,%3}, {%4,%5,%6,%7}, {%8,%9}, {%0,%1,%2,%3};" \
        : "+f"((c)[0]), "+f"((c)[1]), "+f"((c)[2]), "+f"((c)[3]) \
        : "r"((a)[0]), "r"((a)[1]), "r"((a)[2]), "r"((a)[3]), \
          "r"(b0v), "r"(b1v))

#define LDMX4(r, addr) \
    asm volatile("ldmatrix.sync.aligned.m8n8.x4.shared.b16 {%0,%1,%2,%3}, [%4];" \
        : "=r"((r)[0]), "=r"((r)[1]), "=r"((r)[2]), "=r"((r)[3]) : "r"(addr))

__device__ __forceinline__ float wredsum(float v){
    #pragma unroll
    for (int o = 16; o; o >>= 1) v += __shfl_xor_sync(0xFFFFFFFFu, v, o);
    return v;
}
__device__ __forceinline__ float dot4(float4 a, float4 b){
    return fmaf(a.x,b.x, fmaf(a.y,b.y, fmaf(a.z,b.z, a.w*b.w)));
}

// ---------------- K1: A, Bq, K, V ----------------
__global__ void __launch_bounds__(256)
k_pre1(const float* __restrict__ ts_emb, const int* __restrict__ user_x,
       const float* __restrict__ upt,
       const float* __restrict__ Wq, const float* __restrict__ bq,
       const float* __restrict__ Wk, const float* __restrict__ bk,
       const float* __restrict__ Wv, const float* __restrict__ bv)
{
    const int wid  = threadIdx.x >> 5;
    const int lane = threadIdx.x & 31;
    const int rg   = blockIdx.x >> 6;
    const int he   = (blockIdx.x & 63)*8 + wid;

    const float* w;
    const float* x[8];
    float bias = 0.f;
    float* dst;
    int row0;
    if (rg < 8) {
        w = Wq + (size_t)he*1024; dst = g_A; row0 = rg*8;
        #pragma unroll
        for (int i = 0; i < 8; i++)
            x[i] = upt + (size_t)__ldg(user_x + rg*8 + i)*D;
    } else if (rg < 11) {
        int g = rg - 8;
        w = Wq + (size_t)he*1024 + 512; bias = __ldg(bq + he);
        dst = g_Bq; row0 = g*8;
        #pragma unroll
        for (int i = 0; i < 8; i++) x[i] = ts_emb + (g*8 + i)*D;
    } else if (rg < 14) {
        int g = rg - 11;
        w = Wk + (size_t)he*512; bias = __ldg(bk + he);
        dst = g_K; row0 = g*8;
        #pragma unroll
        for (int i = 0; i < 8; i++) x[i] = ts_emb + (g*8 + i)*D;
    } else {
        int g = rg - 14;
        w = Wv + (size_t)he*512; bias = __ldg(bv + he);
        dst = g_V; row0 = g*8;
        #pragma unroll
        for (int i = 0; i < 8; i++) x[i] = ts_emb + (g*8 + i)*D;
    }

    float acc[8] = {0,0,0,0,0,0,0,0};
    #pragma unroll
    for (int ch = 0; ch < 4; ch++) {
        int e = ch*128 + lane*4;
        float4 w4 = __ldg((const float4*)(w + e));
        #pragma unroll
        for (int i = 0; i < 8; i++) {
            float4 x4 = __ldg((const float4*)(x[i] + e));
            acc[i] = fmaf(w4.x,x4.x, fmaf(w4.y,x4.y, fmaf(w4.z,x4.z, fmaf(w4.w,x4.w, acc[i]))));
        }
    }
    float r = 0.f;
    #pragma unroll
    for (int i = 0; i < 8; i++) {
        float s = wredsum(acc[i]);
        if (lane == i) r = s;
    }
    if (lane < 8)
        dst[(size_t)(row0 + lane)*D + he] = r + bias;
}

// ---------------- K23: VU/TL folds + E table ----------------
__global__ void __launch_bounds__(256)
k_pre23(const float* __restrict__ Wu, const float* __restrict__ Wt)
{
    const int wid  = threadIdx.x >> 5;
    const int lane = threadIdx.x & 31;
    if (blockIdx.x < 804) {
        int task = blockIdx.x*8 + wid;
        if (task < 6144) {
            int j  = task >> 6;
            int dg = task & 63;
            int h = j / TS, k = j - h*TS;
            float4 vr = *(const float4*)(g_V + (k*NH + h)*HD + lane*4);
            const float* wbase = Wu + h*HD + lane*4;
            float val = 0.f;
            #pragma unroll
            for (int dd = 0; dd < 8; dd++) {
                int d = dg*8 + dd;
                float4 w4 = __ldg((const float4*)(wbase + (size_t)d*D));
                float s = wredsum(dot4(vr, w4));
                if (lane == dd) val = s;
            }
            if (lane < 8) {
                int d = dg*8 + lane;
                __nv_bfloat16 hi = __float2bfloat16(val);
                __nv_bfloat16 lo = __float2bfloat16(val - __bfloat162float(hi));
                g_Bh[(size_t)d*JP + j] = hi;
                g_Bl[(size_t)d*JP + j] = lo;
            }
        } else if (task < 6144 + 288) {
            int t2 = task - 6144;
            int j  = t2 / 3;
            int dg = t2 - j*3;
            int h = j / TS, k = j - h*TS;
            float4 vr = *(const float4*)(g_V + (k*NH + h)*HD + lane*4);
            const float* wbase = Wt + h*HD + lane*4;
            float val = 0.f;
            #pragma unroll
            for (int dd = 0; dd < 8; dd++) {
                int d = dg*8 + dd;
                float4 w4 = __ldg((const float4*)(wbase + (size_t)d*D));
                float s = wredsum(dot4(vr, w4));
                if (lane == dd) val = s;
            }
            if (lane < 8)
                g_TL[j*TS + dg*8 + lane] = val;
        }
    } else {
        int blk = blockIdx.x - 804;
        int b   = blk / 12;
        int rem = blk - b*12;
        int h   = rem / 3;
        int tg  = rem - h*3;
        int t   = tg*8 + wid;

        float4 qa = *(const float4*)(g_A  + (b*NH + h)*HD + lane*4);
        float4 qb = *(const float4*)(g_Bq + (t*NH + h)*HD + lane*4);
        float4 q = make_float4(qa.x+qb.x, qa.y+qb.y, qa.z+qb.z, qa.w+qb.w);

        float val = 0.f;
        #pragma unroll
        for (int k = 0; k < TS; k++) {
            float4 kv = *(const float4*)(g_K + (k*NH + h)*HD + lane*4);
            float s = wredsum(dot4(q, kv));
            if (lane == k) val = s;
        }
        if (lane < TS)
            g_E[((size_t)(b*TS + t)*NH + h)*TS + lane] = expf(val * 0.08838834764831845f);
    }
}

// ---------------- fused: softmax + A tiles + resident-B HMMA + TL ----------------
#define FM_MBAR  0
#define FM_B     16          /* hi @16, lo @16+26624 */
#define FM_AHI   53264
#define FM_ALO   79888
#define FM_TOTAL 106512
#define LO_OFF   26624

__global__ void __launch_bounds__(256, 2)
k_fused(const int* __restrict__ hour_x, const int* __restrict__ hour_mask,
        const float* __restrict__ b_unify, const float* __restrict__ b_time,
        float* __restrict__ out_emb, float* __restrict__ out_tl)
{
    extern __shared__ char sm[];
    const uint32_t sb = smem_u32(sm);
    const int tid  = threadIdx.x;
    const int wid  = tid >> 5;
    const int lane = tid & 31;
    const int tile = blockIdx.x >> 2;
    const int c    = blockIdx.x & 3;
    const int n0   = tile * 128;

    // kick off resident B-chunk load immediately
    if (tid == 0) {
        MBAR_INIT(sb + FM_MBAR, 1);
        MBAR_EXPECT(sb + FM_MBAR, 2*LO_OFF);
        bulk_g2s(sb + FM_B,          g_Bh + (size_t)c*128*JP, LO_OFF, sb + FM_MBAR);
        bulk_g2s(sb + FM_B + LO_OFF, g_Bl + (size_t)c*128*JP, LO_OFF, sb + FM_MBAR);
    }

    // ---- softmax (registers) + A hi/lo tile writes: tasks (p, h), 2 per thread
    #pragma unroll
    for (int r = 0; r < 2; r++) {
        const int task = r*256 + tid;
        const int p = task & 127;
        const int h = task >> 7;          // 0,1 then 2,3
        const int n = n0 + p;
        const int b = n >> 9;
        const int t = __ldg(hour_x + n);
        const float4* erow = (const float4*)(g_E + ((size_t)(b*TS + t)*NH + h)*TS);
        const int4*   mrow = (const int4*)(hour_mask + (size_t)n*TS);
        float wv[TS]; float sum = 0.f;
        #pragma unroll
        for (int q = 0; q < 6; q++) {
            int4   m = __ldg(mrow + q);
            float4 e = erow[q];
            wv[4*q+0] = (m.x == 1) ? 0.f : e.x;
            wv[4*q+1] = (m.y == 1) ? 0.f : e.y;
            wv[4*q+2] = (m.z == 1) ? 0.f : e.z;
            wv[4*q+3] = (m.w == 1) ? 0.f : e.w;
            sum += (wv[4*q+0]+wv[4*q+1]) + (wv[4*q+2]+wv[4*q+3]);
        }
        const float inv = 1.f / sum;
        uint32_t hiw[12], low[12];
        #pragma unroll
        for (int q = 0; q < 12; q++) {
            float a0 = wv[2*q]*inv, a1 = wv[2*q+1]*inv;
            __nv_bfloat16 h0 = __float2bfloat16(a0);
            __nv_bfloat16 h1 = __float2bfloat16(a1);
            __nv_bfloat16 l0 = __float2bfloat16(a0 - __bfloat162float(h0));
            __nv_bfloat16 l1 = __float2bfloat16(a1 - __bfloat162float(h1));
            hiw[q] = (uint32_t)__bfloat16_as_ushort(h1) << 16 | __bfloat16_as_ushort(h0);
            low[q] = (uint32_t)__bfloat16_as_ushort(l1) << 16 | __bfloat16_as_ushort(l0);
        }
        char* base = sm + FM_AHI + p*208 + h*48;
        uint4* dh = (uint4*)base;
        uint4* dl = (uint4*)(base + LO_OFF);
        dh[0] = make_uint4(hiw[0],hiw[1],hiw[2],hiw[3]);
        dh[1] = make_uint4(hiw[4],hiw[5],hiw[6],hiw[7]);
        dh[2] = make_uint4(hiw[8],hiw[9],hiw[10],hiw[11]);
        dl[0] = make_uint4(low[0],low[1],low[2],low[3]);
        dl[1] = make_uint4(low[4],low[5],low[6],low[7]);
        dl[2] = make_uint4(low[8],low[9],low[10],low[11]);
    }
    __syncthreads();
    MBAR_WAIT(sb + FM_MBAR, 0);

    // ---- HMMA mainloop: 8 warps, warp tile 32x64, all operands resident ----
    const int wm = wid & 3, wn = wid >> 2;
    const int grp = lane >> 2, qid = lane & 3;
    const int am = lane >> 3, r8 = lane & 7;

    const uint32_t aBase = sb + FM_AHI
        + (uint32_t)(wm*32 + (am & 1)*8 + r8)*208u + (uint32_t)((am >> 1) & 1)*16u;
    const uint32_t bLane = (uint32_t)(((am >> 1) & 1)*8 + r8)*208u + (uint32_t)(am & 1)*16u;

    float acc[2][2][4][4];   // [mt][nh][nt][4]
    #pragma unroll
    for (int mt = 0; mt < 2; mt++)
        #pragma unroll
        for (int nh = 0; nh < 2; nh++)
            #pragma unroll
            for (int nt = 0; nt < 4; nt++)
                #pragma unroll
                for (int k = 0; k < 4; k++) acc[mt][nh][nt][k] = 0.f;

    #pragma unroll
    for (int ks = 0; ks < 6; ks++) {
        const uint32_t ak = aBase + ks*32;
        uint32_t ah[2][4], al[2][4];
        LDMX4(ah[0], ak);
        LDMX4(ah[1], ak + 16*208);
        LDMX4(al[0], ak + LO_OFF);
        LDMX4(al[1], ak + LO_OFF + 16*208);
        #pragma unroll
        for (int nh = 0; nh < 2; nh++) {
            const uint32_t bk = sb + FM_B + (uint32_t)(wn*64 + nh*32)*208u + bLane + ks*32;
            uint32_t bh[2][4], bl[2][4];
            LDMX4(bh[0], bk);
            LDMX4(bh[1], bk + 16*208);
            LDMX4(bl[0], bk + LO_OFF);
            LDMX4(bl[1], bk + LO_OFF + 16*208);
            #pragma unroll
            for (int mt = 0; mt < 2; mt++)
                #pragma unroll
                for (int nt = 0; nt < 4; nt++) {
                    const int pr = nt >> 1, sub = (nt & 1)*2;
                    MMA16816(acc[mt][nh][nt], ah[mt], bh[pr][sub], bh[pr][sub+1]);
                    MMA16816(acc[mt][nh][nt], ah[mt], bl[pr][sub], bl[pr][sub+1]);
                    MMA16816(acc[mt][nh][nt], al[mt], bh[pr][sub], bh[pr][sub+1]);
                }
        }
    }

    // ---- store with bias ----
    #pragma unroll
    for (int nh = 0; nh < 2; nh++)
        #pragma unroll
        for (int nt = 0; nt < 4; nt++) {
            int d = c*128 + wn*64 + nh*32 + nt*8 + qid*2;
            float bx = __ldg(b_unify + d), by = __ldg(b_unify + d + 1);
            #pragma unroll
            for (int mt = 0; mt < 2; mt++) {
                int row = n0 + wm*32 + mt*16 + grp;
                float2 o0 = make_float2(acc[mt][nh][nt][0] + bx, acc[mt][nh][nt][1] + by);
                float2 o1 = make_float2(acc[mt][nh][nt][2] + bx, acc[mt][nh][nt][3] + by);
                *(float2*)(out_emb + (size_t)row*D + d)     = o0;
                *(float2*)(out_emb + (size_t)(row+8)*D + d) = o1;
            }
        }

    // ---- time logits: only c==0 CTAs; attn reconstructed from hi+lo tiles ----
    if (c == 0) {
        const int p  = tid >> 1;
        const int d0 = (tid & 1)*12;
        const uint32_t* hiw = (const uint32_t*)(sm + FM_AHI + p*208);
        const uint32_t* low = (const uint32_t*)(sm + FM_ALO + p*208);
        float a12[12];
        #pragma unroll
        for (int i = 0; i < 12; i++) a12[i] = 0.f;
        #pragma unroll 6
        for (int jq = 0; jq < 48; jq++) {
            uint32_t hw = hiw[jq], lw = low[jq];
            float a0 = __uint_as_float(hw << 16)         + __uint_as_float(lw << 16);
            float a1 = __uint_as_float(hw & 0xFFFF0000u) + __uint_as_float(lw & 0xFFFF0000u);
            const float* t0 = g_TL + (jq*2)*TS + d0;
            const float* t1 = t0 + TS;
            #pragma unroll
            for (int i = 0; i < 3; i++) {
                float4 v0 = __ldg((const float4*)(t0 + i*4));
                float4 v1 = __ldg((const float4*)(t1 + i*4));
                a12[i*4+0] = fmaf(a0, v0.x, fmaf(a1, v1.x, a12[i*4+0]));
                a12[i*4+1] = fmaf(a0, v0.y, fmaf(a1, v1.y, a12[i*4+1]));
                a12[i*4+2] = fmaf(a0, v0.z, fmaf(a1, v1.z, a12[i*4+2]));
                a12[i*4+3] = fmaf(a0, v0.w, fmaf(a1, v1.w, a12[i*4+3]));
            }
        }
        float* orow = out_tl + (size_t)(n0 + p)*TS + d0;
        #pragma unroll
        for (int i = 0; i < 12; i++)
            orow[i] = a12[i] + __ldg(b_time + d0 + i);
    }
}

// ---------------- launch ----------------
extern "C" void kernel_launch(void* const* d_in, const int* in_sizes, int n_in,
                              void* d_out, int out_size)
{
    const float* ts_emb    = (const float*)d_in[0];
    const int*   user_x    = (const int*)  d_in[3];
    const int*   hour_x    = (const int*)  d_in[4];
    const int*   hour_mask = (const int*)  d_in[5];
    const float* upt       = (const float*)d_in[6];
    const float* Wq        = (const float*)d_in[7];
    const float* bq        = (const float*)d_in[8];
    const float* Wk        = (const float*)d_in[9];
    const float* bk        = (const float*)d_in[10];
    const float* Wv        = (const float*)d_in[11];
    const float* bv        = (const float*)d_in[12];
    const float* Wu        = (const float*)d_in[13];
    const float* bu        = (const float*)d_in[14];
    const float* Wt        = (const float*)d_in[15];
    const float* bt        = (const float*)d_in[16];

    float* out_emb = (float*)d_out;
    float* out_tl  = out_emb + (size_t)NPOS * D;

    cudaFuncSetAttribute(k_fused, cudaFuncAttributeMaxDynamicSharedMemorySize, FM_TOTAL);

    k_pre1<<<1088, 256>>>(ts_emb, user_x, upt, Wq, bq, Wk, bk, Wv, bv);
    k_pre23<<<1572, 256>>>(Wu, Wt);
    k_fused<<<1024, 256, FM_TOTAL>>>(hour_x, hour_mask, bu, bt, out_emb, out_tl);
}

// round 10
// speedup vs baseline: 2.0203x; 1.6094x over previous
#include <cuda_runtime.h>
#include <cuda_fp16.h>
#include <math.h>
#include <stdint.h>

#define NH 4
#define HD 128
#define D  512
#define TS 24
#define NB 64
#define NPOS 32768
#define J   96
#define JP  104
#define BL  26624     /* bytes per big B half-tile (128 rows x 208B) */
#define TLB 6656      /* bytes per TL half-tile (32 rows x 208B) */

// ---------------- device scratch ----------------
__device__ __align__(16)  float g_A [NB*NH*HD];
__device__ __align__(16)  float g_Bq[TS*NH*HD];
__device__ __align__(16)  float g_K [TS*NH*HD];
__device__ __align__(16)  float g_V [TS*NH*HD];
__device__ __align__(16)  float g_E [NB*TS*NH*TS];
__device__ __align__(128) __half g_Bh[D*JP];     // VU^T hi fp16: [d][j], 208B rows
__device__ __align__(128) __half g_Bl[D*JP];     // VU^T lo fp16
__device__ __align__(128) __half g_Th[32*JP];    // TL hi fp16 (rows 24..31 zero)
__device__ __align__(128) __half g_Tl[32*JP];    // TL lo fp16

// ---------------- helpers ----------------
__device__ __forceinline__ uint32_t smem_u32(const void* p){
    uint32_t a;
    asm("{ .reg .u64 t; cvta.to.shared.u64 t, %1; cvt.u32.u64 %0, t; }" : "=r"(a) : "l"(p));
    return a;
}
__device__ __forceinline__ void bulk_g2s(uint32_t dst, const void* src,
                                         uint32_t bytes, uint32_t mbar){
    asm volatile(
        "cp.async.bulk.shared::cluster.global.mbarrier::complete_tx::bytes [%0], [%1], %2, [%3];"
        :: "r"(dst), "l"(src), "r"(bytes), "r"(mbar) : "memory");
}
#define MBAR_INIT(a, c)  asm volatile("mbarrier.init.shared.b64 [%0], %1;" :: "r"(a), "r"(c) : "memory")
#define MBAR_EXPECT(a,b) asm volatile("mbarrier.arrive.expect_tx.shared.b64 _, [%0], %1;" :: "r"(a), "r"(b) : "memory")
#define MBAR_WAIT(a, ph) do { \
    uint32_t _m=(a), _p=(ph), _d; \
    asm volatile("{\n\t.reg .pred p;\n\t" \
        "mbarrier.try_wait.parity.acquire.cta.shared::cta.b64 p, [%1], %2;\n\t" \
        "selp.b32 %0, 1, 0, p;\n\t}" : "=r"(_d) : "r"(_m), "r"(_p) : "memory"); \
    if (!_d) { asm volatile("{\n\t.reg .pred P1;\n\t" \
        "W_%=:\n\tmbarrier.try_wait.parity.acquire.cta.shared::cta.b64 P1, [%0], %1, 0x989680;\n\t" \
        "@P1 bra.uni WD_%=;\n\tbra.uni W_%=;\n\tWD_%=:\n\t}" :: "r"(_m), "r"(_p) : "memory"); } \
} while(0)

#define MMA16816(c, a, b0v, b1v) \
    asm volatile("mma.sync.aligned.m16n8k16.row.col.f32.f16.f16.f32 " \
        "{%0,%1,%2,%3}, {%4,%5,%6,%7}, {%8,%9}, {%0,%1,%2,%3};" \
        : "+f"((c)[0]), "+f"((c)[1]), "+f"((c)[2]), "+f"((c)[3]) \
        : "r"((a)[0]), "r"((a)[1]), "r"((a)[2]), "r"((a)[3]), \
          "r"(b0v), "r"(b1v))

#define LDMX4(r, addr) \
    asm volatile("ldmatrix.sync.aligned.m8n8.x4.shared.b16 {%0,%1,%2,%3}, [%4];" \
        : "=r"((r)[0]), "=r"((r)[1]), "=r"((r)[2]), "=r"((r)[3]) : "r"(addr))

__device__ __forceinline__ float wredsum(float v){
    #pragma unroll
    for (int o = 16; o; o >>= 1) v += __shfl_xor_sync(0xFFFFFFFFu, v, o);
    return v;
}
__device__ __forceinline__ float dot4(float4 a, float4 b){
    return fmaf(a.x,b.x, fmaf(a.y,b.y, fmaf(a.z,b.z, a.w*b.w)));
}

// ---------------- K1: A, Bq, K, V ----------------
__global__ void __launch_bounds__(256)
k_pre1(const float* __restrict__ ts_emb, const int* __restrict__ user_x,
       const float* __restrict__ upt,
       const float* __restrict__ Wq, const float* __restrict__ bq,
       const float* __restrict__ Wk, const float* __restrict__ bk,
       const float* __restrict__ Wv, const float* __restrict__ bv)
{
    const int wid  = threadIdx.x >> 5;
    const int lane = threadIdx.x & 31;
    const int rg   = blockIdx.x >> 6;
    const int he   = (blockIdx.x & 63)*8 + wid;

    const float* w;
    const float* x[8];
    float bias = 0.f;
    float* dst;
    int row0;
    if (rg < 8) {
        w = Wq + (size_t)he*1024; dst = g_A; row0 = rg*8;
        #pragma unroll
        for (int i = 0; i < 8; i++)
            x[i] = upt + (size_t)__ldg(user_x + rg*8 + i)*D;
    } else if (rg < 11) {
        int g = rg - 8;
        w = Wq + (size_t)he*1024 + 512; bias = __ldg(bq + he);
        dst = g_Bq; row0 = g*8;
        #pragma unroll
        for (int i = 0; i < 8; i++) x[i] = ts_emb + (g*8 + i)*D;
    } else if (rg < 14) {
        int g = rg - 11;
        w = Wk + (size_t)he*512; bias = __ldg(bk + he);
        dst = g_K; row0 = g*8;
        #pragma unroll
        for (int i = 0; i < 8; i++) x[i] = ts_emb + (g*8 + i)*D;
    } else {
        int g = rg - 14;
        w = Wv + (size_t)he*512; bias = __ldg(bv + he);
        dst = g_V; row0 = g*8;
        #pragma unroll
        for (int i = 0; i < 8; i++) x[i] = ts_emb + (g*8 + i)*D;
    }

    float acc[8] = {0,0,0,0,0,0,0,0};
    #pragma unroll
    for (int ch = 0; ch < 4; ch++) {
        int e = ch*128 + lane*4;
        float4 w4 = __ldg((const float4*)(w + e));
        #pragma unroll
        for (int i = 0; i < 8; i++) {
            float4 x4 = __ldg((const float4*)(x[i] + e));
            acc[i] = fmaf(w4.x,x4.x, fmaf(w4.y,x4.y, fmaf(w4.z,x4.z, fmaf(w4.w,x4.w, acc[i]))));
        }
    }
    float r = 0.f;
    #pragma unroll
    for (int i = 0; i < 8; i++) {
        float s = wredsum(acc[i]);
        if (lane == i) r = s;
    }
    if (lane < 8)
        dst[(size_t)(row0 + lane)*D + he] = r + bias;
}

// ---------------- K23: VU/TL folds (fp16 hi/lo) + E table ----------------
__global__ void __launch_bounds__(256)
k_pre23(const float* __restrict__ Wu, const float* __restrict__ Wt)
{
    const int wid  = threadIdx.x >> 5;
    const int lane = threadIdx.x & 31;
    if (blockIdx.x < 804) {
        int task = blockIdx.x*8 + wid;
        if (task < 6144) {
            int j  = task >> 6;
            int dg = task & 63;
            int h = j / TS, k = j - h*TS;
            float4 vr = *(const float4*)(g_V + (k*NH + h)*HD + lane*4);
            const float* wbase = Wu + h*HD + lane*4;
            float val = 0.f;
            #pragma unroll
            for (int dd = 0; dd < 8; dd++) {
                int d = dg*8 + dd;
                float4 w4 = __ldg((const float4*)(wbase + (size_t)d*D));
                float s = wredsum(dot4(vr, w4));
                if (lane == dd) val = s;
            }
            if (lane < 8) {
                int d = dg*8 + lane;
                __half hi = __float2half_rn(val);
                __half lo = __float2half_rn(val - __half2float(hi));
                g_Bh[(size_t)d*JP + j] = hi;
                g_Bl[(size_t)d*JP + j] = lo;
            }
        } else if (task < 6144 + 288) {
            int t2 = task - 6144;
            int j  = t2 / 3;
            int dg = t2 - j*3;
            int h = j / TS, k = j - h*TS;
            float4 vr = *(const float4*)(g_V + (k*NH + h)*HD + lane*4);
            const float* wbase = Wt + h*HD + lane*4;
            float val = 0.f;
            #pragma unroll
            for (int dd = 0; dd < 8; dd++) {
                int d = dg*8 + dd;
                float4 w4 = __ldg((const float4*)(wbase + (size_t)d*D));
                float s = wredsum(dot4(vr, w4));
                if (lane == dd) val = s;
            }
            if (lane < 8) {
                int d = dg*8 + lane;       // < 24
                __half hi = __float2half_rn(val);
                __half lo = __float2half_rn(val - __half2float(hi));
                g_Th[(size_t)d*JP + j] = hi;
                g_Tl[(size_t)d*JP + j] = lo;
            }
        }
    } else {
        int blk = blockIdx.x - 804;
        int b   = blk / 12;
        int rem = blk - b*12;
        int h   = rem / 3;
        int tg  = rem - h*3;
        int t   = tg*8 + wid;

        float4 qa = *(const float4*)(g_A  + (b*NH + h)*HD + lane*4);
        float4 qb = *(const float4*)(g_Bq + (t*NH + h)*HD + lane*4);
        float4 q = make_float4(qa.x+qb.x, qa.y+qb.y, qa.z+qb.z, qa.w+qb.w);

        float val = 0.f;
        #pragma unroll
        for (int k = 0; k < TS; k++) {
            float4 kv = *(const float4*)(g_K + (k*NH + h)*HD + lane*4);
            float s = wredsum(dot4(q, kv));
            if (lane == k) val = s;
        }
        if (lane < TS)
            g_E[((size_t)(b*TS + t)*NH + h)*TS + lane] = expf(val * 0.08838834764831845f);
    }
}

// ---------------- k_main: softmax + A fp16 + 2-pass HMMA, TL via MMA ----------------
#define FM_MBAR  0
#define FM_A     128
#define FM_B     26752            /* B buffer: hi @0, lo @+BL */
#define FM_TOTAL 80000

__global__ void __launch_bounds__(256, 2)
k_main(const int* __restrict__ hour_x, const int* __restrict__ hour_mask,
       const float* __restrict__ b_unify, const float* __restrict__ b_time,
       float* __restrict__ out_emb, float* __restrict__ out_tl)
{
    extern __shared__ char sm[];
    const uint32_t sb = smem_u32(sm);
    const int tid  = threadIdx.x;
    const int wid  = tid >> 5;
    const int lane = tid & 31;
    const int n0   = blockIdx.x * 128;

    // chunk 0 load starts immediately
    if (tid == 0) {
        MBAR_INIT(sb + FM_MBAR, 1);
        MBAR_EXPECT(sb + FM_MBAR, 2*BL);
        bulk_g2s(sb + FM_B,      g_Bh, BL, sb + FM_MBAR);
        bulk_g2s(sb + FM_B + BL, g_Bl, BL, sb + FM_MBAR);
    }

    // ---- softmax (registers) -> A fp16 tile: tasks (p,h), 2/thread ----
    #pragma unroll
    for (int r = 0; r < 2; r++) {
        const int task = r*256 + tid;
        const int p = task & 127;
        const int h = task >> 7;
        const int n = n0 + p;
        const int b = n >> 9;
        const int t = __ldg(hour_x + n);
        const float4* erow = (const float4*)(g_E + ((size_t)(b*TS + t)*NH + h)*TS);
        const int4*   mrow = (const int4*)(hour_mask + (size_t)n*TS);
        float wv[TS]; float sum = 0.f;
        #pragma unroll
        for (int q = 0; q < 6; q++) {
            int4   m = __ldg(mrow + q);
            float4 e = erow[q];
            wv[4*q+0] = (m.x == 1) ? 0.f : e.x;
            wv[4*q+1] = (m.y == 1) ? 0.f : e.y;
            wv[4*q+2] = (m.z == 1) ? 0.f : e.z;
            wv[4*q+3] = (m.w == 1) ? 0.f : e.w;
            sum += (wv[4*q+0]+wv[4*q+1]) + (wv[4*q+2]+wv[4*q+3]);
        }
        const float inv = 1.f / sum;
        uint32_t w12[12];
        #pragma unroll
        for (int q = 0; q < 12; q++) {
            __half h0 = __float2half_rn(wv[2*q]*inv);
            __half h1 = __float2half_rn(wv[2*q+1]*inv);
            w12[q] = (uint32_t)__half_as_ushort(h1) << 16 | __half_as_ushort(h0);
        }
        uint4* dhp = (uint4*)(sm + FM_A + p*208 + h*48);
        dhp[0] = make_uint4(w12[0],w12[1],w12[2],w12[3]);
        dhp[1] = make_uint4(w12[4],w12[5],w12[6],w12[7]);
        dhp[2] = make_uint4(w12[8],w12[9],w12[10],w12[11]);
    }
    __syncthreads();

    // ---- mainloop ----
    const int wm = wid & 3, wn = wid >> 2;
    const int grp = lane >> 2, qid = lane & 3;
    const int am = lane >> 3, r8 = lane & 7;

    const uint32_t aBase = sb + FM_A
        + (uint32_t)(wm*32 + (am & 1)*8 + r8)*208u + (uint32_t)((am >> 1) & 1)*16u;
    const uint32_t bLane = (uint32_t)(((am >> 1) & 1)*8 + r8)*208u + (uint32_t)(am & 1)*16u;

    for (int c = 0; c < 4; c++) {
        MBAR_WAIT(sb + FM_MBAR, c & 1);

        float acc[2][2][4][4];
        #pragma unroll
        for (int mt = 0; mt < 2; mt++)
            #pragma unroll
            for (int nh = 0; nh < 2; nh++)
                #pragma unroll
                for (int nt = 0; nt < 4; nt++)
                    #pragma unroll
                    for (int k = 0; k < 4; k++) acc[mt][nh][nt][k] = 0.f;

        #pragma unroll
        for (int ks = 0; ks < 6; ks++) {
            uint32_t ah[2][4];
            LDMX4(ah[0], aBase + ks*32);
            LDMX4(ah[1], aBase + ks*32 + 16*208);
            #pragma unroll
            for (int nh = 0; nh < 2; nh++) {
                const uint32_t bk = sb + FM_B + (uint32_t)(wn*64 + nh*32)*208u + bLane + ks*32;
                uint32_t bh[2][4], bl[2][4];
                LDMX4(bh[0], bk);
                LDMX4(bh[1], bk + 16*208);
                LDMX4(bl[0], bk + BL);
                LDMX4(bl[1], bk + BL + 16*208);
                #pragma unroll
                for (int mt = 0; mt < 2; mt++)
                    #pragma unroll
                    for (int nt = 0; nt < 4; nt++) {
                        const int pr = nt >> 1, sub = (nt & 1)*2;
                        MMA16816(acc[mt][nh][nt], ah[mt], bh[pr][sub], bh[pr][sub+1]);
                        MMA16816(acc[mt][nh][nt], ah[mt], bl[pr][sub], bl[pr][sub+1]);
                    }
            }
        }

        #pragma unroll
        for (int nh = 0; nh < 2; nh++)
            #pragma unroll
            for (int nt = 0; nt < 4; nt++) {
                int d = c*128 + wn*64 + nh*32 + nt*8 + qid*2;
                float bx = __ldg(b_unify + d), by = __ldg(b_unify + d + 1);
                #pragma unroll
                for (int mt = 0; mt < 2; mt++) {
                    int row = n0 + wm*32 + mt*16 + grp;
                    float2 o0 = make_float2(acc[mt][nh][nt][0] + bx, acc[mt][nh][nt][1] + by);
                    float2 o1 = make_float2(acc[mt][nh][nt][2] + bx, acc[mt][nh][nt][3] + by);
                    *(float2*)(out_emb + (size_t)row*D + d)     = o0;
                    *(float2*)(out_emb + (size_t)(row+8)*D + d) = o1;
                }
            }
        __syncthreads();
        if (tid == 0) {
            if (c < 3) {
                MBAR_EXPECT(sb + FM_MBAR, 2*BL);
                bulk_g2s(sb + FM_B,      g_Bh + (size_t)(c+1)*128*JP, BL, sb + FM_MBAR);
                bulk_g2s(sb + FM_B + BL, g_Bl + (size_t)(c+1)*128*JP, BL, sb + FM_MBAR);
            } else {
                MBAR_EXPECT(sb + FM_MBAR, 2*TLB);
                bulk_g2s(sb + FM_B,      g_Th, TLB, sb + FM_MBAR);
                bulk_g2s(sb + FM_B + BL, g_Tl, TLB, sb + FM_MBAR);
            }
        }
    }

    // ---- TL chunk (32 cols, rows 0..23 stored) ----
    MBAR_WAIT(sb + FM_MBAR, 0);
    if (wn == 0) {
        float acc[2][4][4];
        #pragma unroll
        for (int mt = 0; mt < 2; mt++)
            #pragma unroll
            for (int nt = 0; nt < 4; nt++)
                #pragma unroll
                for (int k = 0; k < 4; k++) acc[mt][nt][k] = 0.f;

        #pragma unroll
        for (int ks = 0; ks < 6; ks++) {
            uint32_t ah[2][4];
            LDMX4(ah[0], aBase + ks*32);
            LDMX4(ah[1], aBase + ks*32 + 16*208);
            const uint32_t bk = sb + FM_B + bLane + ks*32;
            uint32_t bh[2][4], bl[2][4];
            LDMX4(bh[0], bk);
            LDMX4(bh[1], bk + 16*208);
            LDMX4(bl[0], bk + BL);
            LDMX4(bl[1], bk + BL + 16*208);
            #pragma unroll
            for (int mt = 0; mt < 2; mt++)
                #pragma unroll
                for (int nt = 0; nt < 4; nt++) {
                    const int pr = nt >> 1, sub = (nt & 1)*2;
                    MMA16816(acc[mt][nt], ah[mt], bh[pr][sub], bh[pr][sub+1]);
                    MMA16816(acc[mt][nt], ah[mt], bl[pr][sub], bl[pr][sub+1]);
                }
        }
        #pragma unroll
        for (int nt = 0; nt < 3; nt++) {         // d = nt*8+qid*2 <= 22
            int d = nt*8 + qid*2;
            float bx = __ldg(b_time + d), by = __ldg(b_time + d + 1);
            #pragma unroll
            for (int mt = 0; mt < 2; mt++) {
                int row = n0 + wm*32 + mt*16 + grp;
                float2 o0 = make_float2(acc[mt][nt][0] + bx, acc[mt][nt][1] + by);
                float2 o1 = make_float2(acc[mt][nt][2] + bx, acc[mt][nt][3] + by);
                *(float2*)(out_tl + (size_t)row*TS + d)     = o0;
                *(float2*)(out_tl + (size_t)(row+8)*TS + d) = o1;
            }
        }
    }
}

// ---------------- launch ----------------
extern "C" void kernel_launch(void* const* d_in, const int* in_sizes, int n_in,
                              void* d_out, int out_size)
{
    const float* ts_emb    = (const float*)d_in[0];
    const int*   user_x    = (const int*)  d_in[3];
    const int*   hour_x    = (const int*)  d_in[4];
    const int*   hour_mask = (const int*)  d_in[5];
    const float* upt       = (const float*)d_in[6];
    const float* Wq        = (const float*)d_in[7];
    const float* bq        = (const float*)d_in[8];
    const float* Wk        = (const float*)d_in[9];
    const float* bk        = (const float*)d_in[10];
    const float* Wv        = (const float*)d_in[11];
    const float* bv        = (const float*)d_in[12];
    const float* Wu        = (const float*)d_in[13];
    const float* bu        = (const float*)d_in[14];
    const float* Wt        = (const float*)d_in[15];
    const float* bt        = (const float*)d_in[16];

    float* out_emb = (float*)d_out;
    float* out_tl  = out_emb + (size_t)NPOS * D;

    cudaFuncSetAttribute(k_main, cudaFuncAttributeMaxDynamicSharedMemorySize, FM_TOTAL);

    k_pre1<<<1088, 256>>>(ts_emb, user_x, upt, Wq, bq, Wk, bk, Wv, bv);
    k_pre23<<<1572, 256>>>(Wu, Wt);
    k_main<<<256, 256, FM_TOTAL>>>(hour_x, hour_mask, bu, bt, out_emb, out_tl);
}